// round 16
// baseline (speedup 1.0000x reference)
#include <cuda_runtime.h>

// S4/DPLR kernel materialization, H=256, N2=64, RANK=1, CH=1, L=2048.
// Two-phase checkpoint decomposition (R9 retry with both failure causes fixed):
//  K1: one warp/head, STATE-ONLY T=16 blocked recurrence for (NC-1)*K steps,
//      UE constants in SMEM (no register spill), checkpoints every K steps.
//  K2: R7's proven T=8 full body per 256-step chunk, H*NC=2048 independent
//      warps -> throughput-bound (~3.5 warps/SMSP).

typedef unsigned long long u64;
#define NCC 8

__device__ float g_ckpt[256 * NCC * 128];   // [h][c][lane*4]: xr0,xr1,xi0,xi1

__device__ __forceinline__ float wsum(float v) {
    #pragma unroll
    for (int o = 16; o; o >>= 1) v += __shfl_xor_sync(0xffffffffu, v, o);
    return v;
}
__device__ __forceinline__ u64 pk(float x, float y) {
    u64 r; asm("mov.b64 %0,{%1,%2};" : "=l"(r) : "f"(x), "f"(y)); return r;
}
__device__ __forceinline__ float2 up(u64 a) {
    float2 v; asm("mov.b64 {%0,%1},%2;" : "=f"(v.x), "=f"(v.y) : "l"(a)); return v;
}
__device__ __forceinline__ u64 f2fma(u64 a, u64 b, u64 c) {
    u64 d; asm("fma.rn.f32x2 %0,%1,%2,%3;" : "=l"(d) : "l"(a), "l"(b), "l"(c)); return d;
}
__device__ __forceinline__ u64 f2mul(u64 a, u64 b) {
    u64 d; asm("mul.rn.f32x2 %0,%1,%2;" : "=l"(d) : "l"(a), "l"(b)); return d;
}
__device__ __forceinline__ u64 f2add(u64 a, u64 b) {
    u64 d; asm("add.rn.f32x2 %0,%1,%2;" : "=l"(d) : "l"(a), "l"(b)); return d;
}

struct HeadCore {
    float er[2], ei[2], qr[2], qi[2], ur[2], ui[2], c2r[2], c2i[2];
    float xr0[2], xi0[2];   // dB
};

__device__ __forceinline__ void head_setup(
    const float* __restrict__ Ar, const float* __restrict__ Ai,
    const float* __restrict__ Br, const float* __restrict__ Bi,
    const float* __restrict__ Pr, const float* __restrict__ Pi,
    const float* __restrict__ Cr, const float* __restrict__ Ci,
    const float* __restrict__ logdt, int h, int lane, HeadCore& C)
{
    const int base = h * 64 + lane;
    const float dt  = expf(logdt[h]);
    const float del = 0.5f * dt;

    float pr[2], pi[2], d_r[2], d_i[2], mmr[2], mmi[2];
    float red4[4] = {0.f, 0.f, 0.f, 0.f};
    #pragma unroll
    for (int s = 0; s < 2; ++s) {
        const int n = base + 32 * s;
        const float lr = -Ar[n], li = -Ai[n];
        const float ar = 1.f + del * lr, ai = del * li;
        const float mr = 1.f - del * lr, mi = -del * li;
        const float idm = 1.f / (mr * mr + mi * mi);
        d_r[s] = mr * idm; d_i[s] = -mi * idm;
        pr[s] = Pr[n]; pi[s] = Pi[n];
        C.er[s] = d_r[s] * ar - d_i[s] * ai;
        C.ei[s] = d_r[s] * ai + d_i[s] * ar;
        C.qr[s] = d_r[s] * pr[s] - d_i[s] * pi[s];
        C.qi[s] = d_r[s] * pi[s] + d_i[s] * pr[s];
        C.c2r[s] = 2.f * Cr[n]; C.c2i[s] = 2.f * Ci[n];
        const float pp = pr[s] * pr[s] + pi[s] * pi[s];
        red4[0] += d_r[s] * pp; red4[1] += d_i[s] * pp;
        const float zr = dt * Br[n], zi = dt * Bi[n];
        mmr[s] = d_r[s] * zr - d_i[s] * zi;
        mmi[s] = d_r[s] * zi + d_i[s] * zr;
        red4[2] += pr[s] * mmr[s] + pi[s] * mmi[s];
        red4[3] += pr[s] * mmi[s] - pi[s] * mmr[s];
    }
    #pragma unroll
    for (int o = 16; o; o >>= 1)
        #pragma unroll
        for (int k = 0; k < 4; ++k)
            red4[k] += __shfl_xor_sync(0xffffffffu, red4[k], o);

    const float wr0 = 1.f + del * red4[0], wi0 = del * red4[1];
    const float iw = 1.f / (wr0 * wr0 + wi0 * wi0);
    const float gar = del * wr0 * iw, gai = -del * wi0 * iw;
    const float dkr = del * red4[0], dki = del * red4[1];
    const float alr = del - (gar * dkr - gai * dki);
    const float ali = -(gar * dki + gai * dkr);

    #pragma unroll
    for (int s = 0; s < 2; ++s) {
        const float gr2 = pr[s] * C.er[s] + pi[s] * C.ei[s];
        const float gi2 = pr[s] * C.ei[s] - pi[s] * C.er[s];
        C.ur[s] = alr * pr[s] + ali * pi[s] + gar * gr2 - gai * gi2;
        C.ui[s] = -alr * pi[s] + ali * pr[s] + gar * gi2 + gai * gr2;
    }
    const float gtr = gar * red4[2] - gai * red4[3];
    const float gti = gar * red4[3] + gai * red4[2];
    #pragma unroll
    for (int s = 0; s < 2; ++s) {
        C.xr0[s] = mmr[s] - (gtr * C.qr[s] - gti * C.qi[s]);
        C.xi0[s] = mmi[s] - (gtr * C.qi[s] + gti * C.qr[s]);
    }
}

// ==================== K1: state-only checkpoint kernel (T=16) ================
#define T1 16
#define ROWP1 36

__global__ __launch_bounds__(64, 1) void ssm_state_kernel(
    const float* __restrict__ Ar, const float* __restrict__ Ai,
    const float* __restrict__ Br, const float* __restrict__ Bi,
    const float* __restrict__ Pr, const float* __restrict__ Pi,
    const float* __restrict__ Cr, const float* __restrict__ Ci,
    const float* __restrict__ logdt,
    int H, int NB1, int KB)
{
    __shared__ __align__(16) float s_part[2][32 * ROWP1];
    __shared__ __align__(16) float s_res[2][32];
    __shared__ __align__(16) ulonglong2 s_ue[2][T1][32];   // (UEr, UEi) per lane

    const int wip = threadIdx.x >> 5;
    const int lane = threadIdx.x & 31;
    const int h = blockIdx.x * 2 + wip;
    if (h >= H) return;

    HeadCore C;
    head_setup(Ar, Ai, Br, Bi, Pr, Pi, Cr, Ci, logdt, h, lane, C);

    // powers m=0..T1-1: UE -> smem, q powers kept for R build
    float qer[T1][2], qei[T1][2];
    float eTr[2], eTi[2];
    {
        float emr[2] = {1.f, 1.f}, emi[2] = {0.f, 0.f};
        #pragma unroll
        for (int m = 0; m < T1; ++m) {
            float uer[2], uei[2];
            #pragma unroll
            for (int s = 0; s < 2; ++s) {
                qer[m][s] = C.qr[s] * emr[s] - C.qi[s] * emi[s];
                qei[m][s] = C.qr[s] * emi[s] + C.qi[s] * emr[s];
                uer[s] = C.ur[s] * emr[s] - C.ui[s] * emi[s];
                uei[s] = C.ur[s] * emi[s] + C.ui[s] * emr[s];
                const float t2 = emr[s] * C.er[s] - emi[s] * C.ei[s];
                emi[s] = emr[s] * C.ei[s] + emi[s] * C.er[s];
                emr[s] = t2;
            }
            s_ue[wip][m][lane] =
                make_ulonglong2(pk(uer[0], uer[1]), pk(uei[0], uei[1]));
        }
        eTr[0] = emr[0]; eTi[0] = emi[0]; eTr[1] = emr[1]; eTi[1] = emi[1];
    }
    __syncwarp();

    // nu_m = u^T E^m q (m=0..T1-2)
    float red[2 * (T1 - 1)];
    #pragma unroll
    for (int m = 0; m < T1 - 1; ++m) {
        float a = 0.f, b = 0.f;
        #pragma unroll
        for (int s = 0; s < 2; ++s) {
            a += C.ur[s] * qer[m][s] - C.ui[s] * qei[m][s];
            b += C.ur[s] * qei[m][s] + C.ui[s] * qer[m][s];
        }
        red[2 * m] = a; red[2 * m + 1] = b;
    }
    #pragma unroll
    for (int o = 16; o; o >>= 1)
        #pragma unroll
        for (int k = 0; k < 2 * (T1 - 1); ++k)
            red[k] += __shfl_xor_sync(0xffffffffu, red[k], o);

    // beta = power-series inverse of (1 + z*nu)
    float btr[T1], bti[T1];
    btr[0] = 1.f; bti[0] = 0.f;
    #pragma unroll
    for (int m = 1; m < T1; ++m) {
        float a = 0.f, b = 0.f;
        #pragma unroll
        for (int j = 0; j < m; ++j) {
            const float nr = red[2 * (m - 1 - j)], ni = red[2 * (m - 1 - j) + 1];
            a -= nr * btr[j] - ni * bti[j];
            b -= nr * bti[j] + ni * btr[j];
        }
        btr[m] = a; bti[m] = b;
    }

    // R_i = sum_{j>=i} beta_{j-i} E^{T1-1-j} q  (positive, packed)
    u64 Rr[T1], Ri[T1];
    #pragma unroll
    for (int i = 0; i < T1; ++i) {
        float rr[2] = {0.f, 0.f}, ri[2] = {0.f, 0.f};
        #pragma unroll
        for (int j = i; j < T1; ++j) {
            const float br2 = btr[j - i], bi2 = bti[j - i];
            #pragma unroll
            for (int s = 0; s < 2; ++s) {
                rr[s] += br2 * qer[T1 - 1 - j][s] - bi2 * qei[T1 - 1 - j][s];
                ri[s] += br2 * qei[T1 - 1 - j][s] + bi2 * qer[T1 - 1 - j][s];
            }
        }
        Rr[i] = pk(rr[0], rr[1]);
        Ri[i] = pk(ri[0], ri[1]);
    }

    const u64 ETr = pk(eTr[0], eTr[1]);
    const u64 ETi = pk(eTi[0], eTi[1]);
    const u64 NEG1 = pk(-1.f, -1.f);
    const u64 ZERO = pk(0.f, 0.f);

    u64 Xr = pk(C.xr0[0], C.xr0[1]);
    u64 Xi = pk(C.xi0[0], C.xi0[1]);

    float* const sp = &s_part[wip][0];
    float* const sr_ = &s_res[wip][0];
    const float4* const rowp = reinterpret_cast<const float4*>(sp + lane * ROWP1);
    const ulonglong2* const uep = &s_ue[wip][0][0];

    int next = KB, cidx = 1;

    #pragma unroll 1
    for (int b = 0; b < NB1; ++b) {
        const u64 XiN = f2mul(Xi, NEG1);

        // mu dots: rows m (mur), 16+m (mui); UE from smem
        #pragma unroll
        for (int m = 0; m < T1; ++m) {
            const ulonglong2 ue = uep[m * 32 + lane];
            float2 a = up(f2fma(ue.y, XiN, f2mul(ue.x, Xr)));
            float2 b2 = up(f2fma(ue.y, Xr,  f2mul(ue.x, Xi)));
            sp[m * ROWP1 + lane]        = a.x + a.y;
            sp[(16 + m) * ROWP1 + lane] = b2.x + b2.y;
        }
        __syncwarp();

        // rowsum: lane sums row 'lane' (32 floats, R7 float4 pattern)
        {
            float4 v0 = rowp[0], v1 = rowp[1], v2 = rowp[2], v3 = rowp[3];
            float4 v4 = rowp[4], v5 = rowp[5], v6 = rowp[6], v7 = rowp[7];
            float4 t0 = make_float4(v0.x + v4.x, v0.y + v4.y, v0.z + v4.z, v0.w + v4.w);
            float4 t1 = make_float4(v1.x + v5.x, v1.y + v5.y, v1.z + v5.z, v1.w + v5.w);
            float4 t2 = make_float4(v2.x + v6.x, v2.y + v6.y, v2.z + v6.z, v2.w + v6.w);
            float4 t3 = make_float4(v3.x + v7.x, v3.y + v7.y, v3.z + v7.z, v3.w + v7.w);
            float4 u0 = make_float4(t0.x + t2.x, t0.y + t2.y, t0.z + t2.z, t0.w + t2.w);
            float4 u1 = make_float4(t1.x + t3.x, t1.y + t3.y, t1.z + t3.z, t1.w + t3.w);
            float4 ww = make_float4(u0.x + u1.x, u0.y + u1.y, u0.z + u1.z, u0.w + u1.w);
            sr_[lane] = (ww.x + ww.y) + (ww.z + ww.w);
        }
        __syncwarp();

        // broadcast mu
        float mur[T1], mui[T1];
        #pragma unroll
        for (int k = 0; k < 4; ++k) {
            const float4 a = *reinterpret_cast<const float4*>(sr_ + 4 * k);
            mur[4 * k] = a.x; mur[4 * k + 1] = a.y;
            mur[4 * k + 2] = a.z; mur[4 * k + 3] = a.w;
            const float4 bb = *reinterpret_cast<const float4*>(sr_ + 16 + 4 * k);
            mui[4 * k] = bb.x; mui[4 * k + 1] = bb.y;
            mui[4 * k + 2] = bb.z; mui[4 * k + 3] = bb.w;
        }

        // update: X' = E^T1.*X - sum_i mu_i.*R_i   (four chains)
        {
            u64 A0 = f2fma(ETi, XiN, f2mul(ETr, Xr));
            u64 B0 = f2fma(ETi, Xr,  f2mul(ETr, Xi));
            u64 A1 = ZERO, B1 = ZERO, A2 = ZERO, B2 = ZERO, A3 = ZERO, B3 = ZERO;
            #pragma unroll
            for (int i = 0; i < T1; i += 4) {
                const u64 a0 = pk(-mur[i], -mur[i]);
                const u64 b0 = pk(mui[i], mui[i]);
                const u64 c0 = pk(-mui[i], -mui[i]);
                A0 = f2fma(a0, Rr[i], f2fma(b0, Ri[i], A0));
                B0 = f2fma(a0, Ri[i], f2fma(c0, Rr[i], B0));
                const u64 a1 = pk(-mur[i + 1], -mur[i + 1]);
                const u64 b1 = pk(mui[i + 1], mui[i + 1]);
                const u64 c1 = pk(-mui[i + 1], -mui[i + 1]);
                A1 = f2fma(a1, Rr[i + 1], f2fma(b1, Ri[i + 1], A1));
                B1 = f2fma(a1, Ri[i + 1], f2fma(c1, Rr[i + 1], B1));
                const u64 a2 = pk(-mur[i + 2], -mur[i + 2]);
                const u64 b2 = pk(mui[i + 2], mui[i + 2]);
                const u64 c2 = pk(-mui[i + 2], -mui[i + 2]);
                A2 = f2fma(a2, Rr[i + 2], f2fma(b2, Ri[i + 2], A2));
                B2 = f2fma(a2, Ri[i + 2], f2fma(c2, Rr[i + 2], B2));
                const u64 a3 = pk(-mur[i + 3], -mur[i + 3]);
                const u64 b3 = pk(mui[i + 3], mui[i + 3]);
                const u64 c3 = pk(-mui[i + 3], -mui[i + 3]);
                A3 = f2fma(a3, Rr[i + 3], f2fma(b3, Ri[i + 3], A3));
                B3 = f2fma(a3, Ri[i + 3], f2fma(c3, Rr[i + 3], B3));
            }
            Xr = f2add(f2add(A0, A1), f2add(A2, A3));
            Xi = f2add(f2add(B0, B1), f2add(B2, B3));
        }

        // checkpoint
        if (b + 1 == next) {
            const float2 a = up(Xr), b2 = up(Xi);
            *reinterpret_cast<float4*>(
                &g_ckpt[(h * NCC + cidx) * 128 + lane * 4]) =
                make_float4(a.x, a.y, b2.x, b2.y);
            next += KB; ++cidx;
        }
    }
}

// ==================== K2: per-chunk output kernel (R7 body, T=8) =============
#define T 8
#define ROWP 36

__global__ __launch_bounds__(128, 1) void ssm_out_kernel(
    const float* __restrict__ Ar, const float* __restrict__ Ai,
    const float* __restrict__ Br, const float* __restrict__ Bi,
    const float* __restrict__ Pr, const float* __restrict__ Pi,
    const float* __restrict__ Cr, const float* __restrict__ Ci,
    const float* __restrict__ logdt,
    float* __restrict__ out, int H, int L, int NC, int K)
{
    __shared__ __align__(16) float s_part[4][24 * ROWP];
    __shared__ __align__(16) float s_res[4][32];

    const int wip = threadIdx.x >> 5;
    const int lane = threadIdx.x & 31;
    const int g = blockIdx.x * 4 + wip;
    if (g >= H * NC) return;
    const int h = g / NC;
    const int c = g - h * NC;

    HeadCore C;
    head_setup(Ar, Ai, Br, Bi, Pr, Pi, Cr, Ci, logdt, h, lane, C);

    // powers m=0..T-1
    float qer[T][2], qei[T][2], uer[T][2], uei[T][2], cer[T][2], cei[T][2];
    float e8r[2], e8i[2];
    {
        float emr[2] = {1.f, 1.f}, emi[2] = {0.f, 0.f};
        #pragma unroll
        for (int m = 0; m < T; ++m) {
            #pragma unroll
            for (int s = 0; s < 2; ++s) {
                qer[m][s] = C.qr[s] * emr[s] - C.qi[s] * emi[s];
                qei[m][s] = C.qr[s] * emi[s] + C.qi[s] * emr[s];
                uer[m][s] = C.ur[s] * emr[s] - C.ui[s] * emi[s];
                uei[m][s] = C.ur[s] * emi[s] + C.ui[s] * emr[s];
                cer[m][s] = C.c2r[s] * emr[s] - C.c2i[s] * emi[s];
                cei[m][s] = C.c2r[s] * emi[s] + C.c2i[s] * emr[s];
                const float t2 = emr[s] * C.er[s] - emi[s] * C.ei[s];
                emi[s] = emr[s] * C.ei[s] + emi[s] * C.er[s];
                emr[s] = t2;
            }
        }
        e8r[0] = emr[0]; e8i[0] = emi[0]; e8r[1] = emr[1]; e8i[1] = emi[1];
    }

    // nu_m, eta_m for m=0..T-2
    float red[4 * (T - 1)];
    #pragma unroll
    for (int m = 0; m < T - 1; ++m) {
        float a = 0.f, b = 0.f, cc = 0.f, d = 0.f;
        #pragma unroll
        for (int s = 0; s < 2; ++s) {
            a  += C.ur[s] * qer[m][s] - C.ui[s] * qei[m][s];
            b  += C.ur[s] * qei[m][s] + C.ui[s] * qer[m][s];
            cc += C.c2r[s] * qer[m][s] - C.c2i[s] * qei[m][s];
            d  += C.c2r[s] * qei[m][s] + C.c2i[s] * qer[m][s];
        }
        red[4 * m] = a; red[4 * m + 1] = b; red[4 * m + 2] = cc; red[4 * m + 3] = d;
    }
    #pragma unroll
    for (int o = 16; o; o >>= 1)
        #pragma unroll
        for (int k = 0; k < 4 * (T - 1); ++k)
            red[k] += __shfl_xor_sync(0xffffffffu, red[k], o);

    float nur[T - 1], nui[T - 1], etr[T - 1], eti[T - 1];
    #pragma unroll
    for (int m = 0; m < T - 1; ++m) {
        nur[m] = red[4 * m];     nui[m] = red[4 * m + 1];
        etr[m] = red[4 * m + 2]; eti[m] = red[4 * m + 3];
    }

    float btr[T], bti[T];
    btr[0] = 1.f; bti[0] = 0.f;
    #pragma unroll
    for (int m = 1; m < T; ++m) {
        float a = 0.f, b = 0.f;
        #pragma unroll
        for (int j = 0; j < m; ++j) {
            a -= nur[m - 1 - j] * btr[j] - nui[m - 1 - j] * bti[j];
            b -= nur[m - 1 - j] * bti[j] + nui[m - 1 - j] * btr[j];
        }
        btr[m] = a; bti[m] = b;
    }
    float wcr[T - 1], wci[T - 1];
    #pragma unroll
    for (int m = 0; m < T - 1; ++m) {
        float a = 0.f, b = 0.f;
        #pragma unroll
        for (int j = 0; j <= m; ++j) {
            a += etr[j] * btr[m - j] - eti[j] * bti[m - j];
            b += etr[j] * bti[m - j] + eti[j] * btr[m - j];
        }
        wcr[m] = a; wci[m] = b;
    }

    float rrr[T][2], rri[T][2];
    #pragma unroll
    for (int i = 0; i < T; ++i) {
        #pragma unroll
        for (int s = 0; s < 2; ++s) { rrr[i][s] = 0.f; rri[i][s] = 0.f; }
        #pragma unroll
        for (int j = i; j < T; ++j) {
            const float br2 = btr[j - i], bi2 = bti[j - i];
            #pragma unroll
            for (int s = 0; s < 2; ++s) {
                rrr[i][s] += br2 * qer[T - 1 - j][s] - bi2 * qei[T - 1 - j][s];
                rri[i][s] += br2 * qei[T - 1 - j][s] + bi2 * qer[T - 1 - j][s];
            }
        }
    }

    u64 UEr[T], UEi[T], CEr[T], CEi[T], Rr[T], Ri[T];
    #pragma unroll
    for (int m = 0; m < T; ++m) {
        UEr[m] = pk(uer[m][0], uer[m][1]);
        UEi[m] = pk(uei[m][0], uei[m][1]);
        CEr[m] = pk(cer[m][0], cer[m][1]);
        CEi[m] = pk(cei[m][0], cei[m][1]);
        Rr[m]  = pk(rrr[m][0], rrr[m][1]);
        Ri[m]  = pk(rri[m][0], rri[m][1]);
    }
    const u64 E8r = pk(e8r[0], e8r[1]);
    const u64 E8i = pk(e8i[0], e8i[1]);
    const u64 NEG1 = pk(-1.f, -1.f);
    const u64 ZERO = pk(0.f, 0.f);

    // initial state for this chunk
    u64 Xr, Xi;
    if (c == 0) {
        Xr = pk(C.xr0[0], C.xr0[1]);
        Xi = pk(C.xi0[0], C.xi0[1]);
    } else {
        const float4 xv = *reinterpret_cast<const float4*>(
            &g_ckpt[(h * NCC + c) * 128 + lane * 4]);
        Xr = pk(xv.x, xv.y);
        Xi = pk(xv.z, xv.w);
    }

    const int len = (c == NC - 1) ? (L - c * K) : K;
    const int NB = len / T;
    float* __restrict__ o_ptr = out + (long)h * L + (long)c * K;

    float* const sp = &s_part[wip][0];
    float* const sr_ = &s_res[wip][0];

    const int row = (lane >= 24) ? (lane - 24) : lane;
    const float4* const rowp = reinterpret_cast<const float4*>(sp + row * ROWP);

    const int mo = lane & 7;
    float mwr[T - 1], mwi[T - 1];
    int mix0[T - 1], mix1[T - 1];
    #pragma unroll
    for (int d = 0; d < T - 1; ++d) {
        const bool act = d < mo;
        const int idx = act ? (mo - 1 - d) : 0;
        mwr[d] = act ? -wcr[d] : 0.f;
        mwi[d] = act ? wci[d] : 0.f;
        mix0[d] = idx;
        mix1[d] = 8 + idx;
    }
    const bool do_store = (lane < 8);

    #pragma unroll 1
    for (int b = 0; b < NB; ++b) {
        const u64 XiN = f2mul(Xi, NEG1);

        #pragma unroll
        for (int m = 0; m < T; ++m) {
            float2 a = up(f2fma(UEi[m], XiN, f2mul(UEr[m], Xr)));
            float2 b2 = up(f2fma(UEi[m], Xr,  f2mul(UEr[m], Xi)));
            float2 cc = up(f2fma(CEi[m], XiN, f2mul(CEr[m], Xr)));
            sp[m * ROWP + lane]        = a.x + a.y;
            sp[(8 + m) * ROWP + lane]  = b2.x + b2.y;
            sp[(16 + m) * ROWP + lane] = cc.x + cc.y;
        }
        __syncwarp();

        {
            float4 v0 = rowp[0], v1 = rowp[1], v2 = rowp[2], v3 = rowp[3];
            float4 v4 = rowp[4], v5 = rowp[5], v6 = rowp[6], v7 = rowp[7];
            float4 t0 = make_float4(v0.x + v4.x, v0.y + v4.y, v0.z + v4.z, v0.w + v4.w);
            float4 t1 = make_float4(v1.x + v5.x, v1.y + v5.y, v1.z + v5.z, v1.w + v5.w);
            float4 t2 = make_float4(v2.x + v6.x, v2.y + v6.y, v2.z + v6.z, v2.w + v6.w);
            float4 t3 = make_float4(v3.x + v7.x, v3.y + v7.y, v3.z + v7.z, v3.w + v7.w);
            float4 u0 = make_float4(t0.x + t2.x, t0.y + t2.y, t0.z + t2.z, t0.w + t2.w);
            float4 u1 = make_float4(t1.x + t3.x, t1.y + t3.y, t1.z + t3.z, t1.w + t3.w);
            float4 ww = make_float4(u0.x + u1.x, u0.y + u1.y, u0.z + u1.z, u0.w + u1.w);
            sr_[lane] = (ww.x + ww.y) + (ww.z + ww.w);
        }
        __syncwarp();

        const float4 m0 = *reinterpret_cast<const float4*>(sr_ + 0);
        const float4 m1 = *reinterpret_cast<const float4*>(sr_ + 4);
        const float4 n0 = *reinterpret_cast<const float4*>(sr_ + 8);
        const float4 n1 = *reinterpret_cast<const float4*>(sr_ + 12);
        const float mur[T] = {m0.x, m0.y, m0.z, m0.w, m1.x, m1.y, m1.z, m1.w};
        const float mui[T] = {n0.x, n0.y, n0.z, n0.w, n1.x, n1.y, n1.z, n1.w};

        {
            u64 A0 = f2fma(E8i, XiN, f2mul(E8r, Xr));
            u64 B0 = f2fma(E8i, Xr,  f2mul(E8r, Xi));
            u64 A1 = ZERO, B1 = ZERO;
            #pragma unroll
            for (int i = 0; i < T; i += 2) {
                const u64 a0 = pk(-mur[i], -mur[i]);
                const u64 b0 = pk(mui[i], mui[i]);
                const u64 c0 = pk(-mui[i], -mui[i]);
                A0 = f2fma(a0, Rr[i], f2fma(b0, Ri[i], A0));
                B0 = f2fma(a0, Ri[i], f2fma(c0, Rr[i], B0));
                const u64 a1 = pk(-mur[i + 1], -mur[i + 1]);
                const u64 b1 = pk(mui[i + 1], mui[i + 1]);
                const u64 c1 = pk(-mui[i + 1], -mui[i + 1]);
                A1 = f2fma(a1, Rr[i + 1], f2fma(b1, Ri[i + 1], A1));
                B1 = f2fma(a1, Ri[i + 1], f2fma(c1, Rr[i + 1], B1));
            }
            Xr = f2add(A0, A1);
            Xi = f2add(B0, B1);
        }

        {
            float kv = sr_[16 + mo];
            #pragma unroll
            for (int d = 0; d < T - 1; ++d)
                kv = fmaf(mwr[d], sr_[mix0[d]], fmaf(mwi[d], sr_[mix1[d]], kv));
            if (do_store) o_ptr[b * T + mo] = kv;
        }
    }

    // scalar tail (only last chunk when L % 8 != 0)
    for (int l = NB * T; l < len; ++l) {
        float2 xr2 = up(Xr), xi2 = up(Xi);
        float xrr[2] = {xr2.x, xr2.y}, xii[2] = {xi2.x, xi2.y};
        float sr2 = 0.f, si2 = 0.f, kv = 0.f;
        #pragma unroll
        for (int s = 0; s < 2; ++s) {
            sr2 += C.ur[s] * xrr[s] - C.ui[s] * xii[s];
            si2 += C.ur[s] * xii[s] + C.ui[s] * xrr[s];
            kv  += C.c2r[s] * xrr[s] - C.c2i[s] * xii[s];
        }
        sr2 = wsum(sr2); si2 = wsum(si2); kv = wsum(kv);
        if (lane == 0) o_ptr[l] = kv;
        float nxr[2], nxi[2];
        #pragma unroll
        for (int s = 0; s < 2; ++s) {
            nxr[s] = C.er[s] * xrr[s] - C.ei[s] * xii[s]
                   - (sr2 * C.qr[s] - si2 * C.qi[s]);
            nxi[s] = C.er[s] * xii[s] + C.ei[s] * xrr[s]
                   - (sr2 * C.qi[s] + si2 * C.qr[s]);
        }
        Xr = pk(nxr[0], nxr[1]); Xi = pk(nxi[0], nxi[1]);
    }
}

extern "C" void kernel_launch(void* const* d_in, const int* in_sizes, int n_in,
                              void* d_out, int out_size) {
    const float* Ar = (const float*)d_in[0];
    const float* Ai = (const float*)d_in[1];
    const float* Br = (const float*)d_in[2];
    const float* Bi = (const float*)d_in[3];
    const float* Pr = (const float*)d_in[4];
    const float* Pi = (const float*)d_in[5];
    const float* Cr = (const float*)d_in[6];
    const float* Ci = (const float*)d_in[7];
    const float* ld = (const float*)d_in[8];
    float* out = (float*)d_out;

    const int H = in_sizes[8];          // 256
    const int L = out_size / H;         // 2048

    int NC = NCC, K = L / NCC;
    const bool chunky = (H <= 256) && (L % NCC == 0) &&
                        (K % T1 == 0) && (K % T == 0);
    if (!chunky) { NC = 1; K = L; }

    if (NC > 1) {
        const int KB = K / T1;                   // blocks per chunk in K1
        const int NB1 = (NC - 1) * KB;           // K1 total blocks
        ssm_state_kernel<<<(H + 1) / 2, 64>>>(
            Ar, Ai, Br, Bi, Pr, Pi, Cr, Ci, ld, H, NB1, KB);
    }
    const int nwarps = H * NC;
    ssm_out_kernel<<<(nwarps + 3) / 4, 128>>>(
        Ar, Ai, Br, Bi, Pr, Pi, Cr, Ci, ld, out, H, L, NC, K);
}